// round 11
// baseline (speedup 1.0000x reference)
#include <cuda_runtime.h>
#include <math.h>

#define T_LEN    1048576
#define L_CHUNK  2048
#define K_CHUNKS (T_LEN / L_CHUNK)   // 512
#define SPI      256                 // samples per warp-iteration per chunk
#define ITERS    (L_CHUNK / SPI)     // 8
#define NC_MAX   32

// ILP=2 (two adjacent chunks per warp) + Horner lane contributions +
// COMPACT MATRIX POWERS: every power of the companion matrix
// M = [[-A1,1],[-A2,0]] has the form [[c,d],[-A2*d, c+A1*d]], so each scan
// level / lane power / carry matrix is stored as 2 scalars instead of 4.
// This halves the persistent constant registers; __launch_bounds__(128,6)
// enforces <=85 regs so 6 blocks/SM fit (24 warps -> more lines in flight).
__global__ __launch_bounds__(128, 6) void peak_fused(
    const float* __restrict__ x, float* __restrict__ y,
    const float* __restrict__ freq_raw, const float* __restrict__ Q_raw,
    const float* __restrict__ gain, int nc)
{
    int tid  = threadIdx.x;
    int lane = tid & 31;
    int gwid = blockIdx.x * 4 + (tid >> 5);          // warp id, 2 chunks each
    int ch = gwid / (K_CHUNKS / 2);
    int k0 = (gwid % (K_CHUNKS / 2)) * 2;            // first of the chunk pair
    if (ch >= nc) return;

    // ---- fp32 coefficient setup (per-warp, transient registers) ----
    const float SR = 44100.0f, MIN_F = 33.0f, MAX_F = 17500.0f, MIN_Q = 0.2f, MAX_Q = 20.0f;
    const float PI = 3.14159265358979323846f;
    float fr = freq_raw[0], qr = Q_raw[0], gn = gain[0];
    float freq = 1.0f / (1.0f + expf(-fr)) * (MAX_F - MIN_F) + MIN_F;
    float Q    = 1.0f / (1.0f + expf(-qr)) * (MAX_Q - MIN_Q) + MIN_Q;
    float w0c  = 2.0f * PI * freq / SR;
    float Ag   = powf(10.0f, gn * 0.025f);
    float alpha = sinf(w0c) / (2.0f * Q);
    float a0inv = 1.0f / (1.0f + alpha / Ag);
    float b0 = (1.0f + alpha * Ag) * a0inv;
    float b1 = (-2.0f * cosf(w0c)) * a0inv;
    float b2 = (1.0f - alpha * Ag) * a0inv;
    float A1 = b1;
    float A2 = (1.0f - alpha / Ag) * a0inv;
    float nA1 = -A1, nA2 = -A2;                       // M = [[-A1,1],[-A2,0]]
    float v0 = fmaf(nA1, b0, b1), v1 = fmaf(nA2, b0, b2);

    // p2[j] ~ M^(2^j) in (c,d) form, j = 0..8.
    // squaring: c' = c*c - A2*d*d ; d' = d*(2c + A1*d)
    float pc[9], pd[9];
    pc[0] = nA1; pd[0] = 1.0f;
    #pragma unroll
    for (int j = 1; j < 9; j++) {
        float c = pc[j-1], d = pd[j-1];
        pc[j] = fmaf(c, c, (nA2 * d) * d);
        pd[j] = d * fmaf(A1, d, 2.0f * c);
    }

    // scan levels l=0..4: (cL,dL) = M^(8*2^l) = p2[l+3]
    float cL[5], dL[5];
    #pragma unroll
    for (int l = 0; l < 5; l++) { cL[l] = pc[l+3]; dL[l] = pd[l+3]; }

    // composition (c1,d1)*(c2,d2): c = c1c2 - A2 d1 d2 ; d = c1 d2 + d1 c2 + A1 d1 d2
    // Pl = M^(8*lane); Rl = M^(8*(31-lane)) (warmup only). Identity = (1,0).
    float Pc = 1.f, Pd = 0.f;
    #pragma unroll
    for (int l = 0; l < 5; l++) {
        if ((lane >> l) & 1) {
            float dd = Pd * pd[l+3];
            float c  = fmaf(Pc, pc[l+3], nA2 * dd);
            float d  = fmaf(Pc, pd[l+3], fmaf(Pd, pc[l+3], A1 * dd));
            Pc = c; Pd = d;
        }
    }
    float Rc = 1.f, Rd = 0.f;
    {
        int rl = 31 - lane;
        #pragma unroll
        for (int l = 0; l < 5; l++) {
            if ((rl >> l) & 1) {
                float dd = Rd * pd[l+3];
                float c  = fmaf(Rc, pc[l+3], nA2 * dd);
                float d  = fmaf(Rc, pd[l+3], fmaf(Rd, pc[l+3], A1 * dd));
                Rc = c; Rd = d;
            }
        }
    }
    float Mc = pc[8], Md = pd[8];                    // M^256 carry, (c,d) form

    size_t offA = (size_t)ch * T_LEN + (size_t)k0 * L_CHUNK;
    size_t offB = offA + L_CHUNK;
    const float4* xpA = (const float4*)(x + offA);
    const float4* xpB = (const float4*)(x + offB);
    float4*       ypA = (float4*)(y + offA);
    float4*       ypB = (float4*)(y + offB);

    // ---- warmups (both chunks, interleaved for MLP) ----
    float sbA0 = 0.f, sbA1 = 0.f, sbB0 = 0.f, sbB1 = 0.f;
    {
        float4 wa0, wa1, wb0, wb1;
        bool hasA = (k0 > 0);
        if (hasA) {
            const float4* wp = (const float4*)(x + offA - SPI);
            wa0 = wp[2 * lane]; wa1 = wp[2 * lane + 1];
        }
        {
            const float4* wp = (const float4*)(x + offB - SPI);
            wb0 = wp[2 * lane]; wb1 = wp[2 * lane + 1];
        }
        float wxA[8] = { wa0.x, wa0.y, wa0.z, wa0.w, wa1.x, wa1.y, wa1.z, wa1.w };
        float wxB[8] = { wb0.x, wb0.y, wb0.z, wb0.w, wb1.x, wb1.y, wb1.z, wb1.w };
        // Horner: h <- M h + v*x
        float hA0 = v0 * wxA[0], hA1 = v1 * wxA[0];
        float hB0 = v0 * wxB[0], hB1 = v1 * wxB[0];
        #pragma unroll
        for (int j = 1; j < 8; j++) {
            float tA0 = fmaf(nA1, hA0, hA1), tA1 = nA2 * hA0;
            float tB0 = fmaf(nA1, hB0, hB1), tB1 = nA2 * hB0;
            hA0 = fmaf(v0, wxA[j], tA0);  hA1 = fmaf(v1, wxA[j], tA1);
            hB0 = fmaf(v0, wxB[j], tB0);  hB1 = fmaf(v1, wxB[j], tB1);
        }
        // position weight: a = R * h, R row2 reconstructed from (Rc,Rd)
        float Rt2 = nA2 * Rd, Rt3 = fmaf(A1, Rd, Rc);
        float aA0 = fmaf(Rc, hA0, Rd * hA1);
        float aA1 = fmaf(Rt2, hA0, Rt3 * hA1);
        float aB0 = fmaf(Rc, hB0, Rd * hB1);
        float aB1 = fmaf(Rt2, hB0, Rt3 * hB1);
        if (!hasA) { aA0 = 0.f; aA1 = 0.f; }
        #pragma unroll
        for (int d = 16; d > 0; d >>= 1) {
            aA0 += __shfl_xor_sync(0xffffffffu, aA0, d);
            aA1 += __shfl_xor_sync(0xffffffffu, aA1, d);
            aB0 += __shfl_xor_sync(0xffffffffu, aB0, d);
            aB1 += __shfl_xor_sync(0xffffffffu, aB1, d);
        }
        if (hasA) { sbA0 = aA0; sbA1 = aA1; }
        sbB0 = aB0; sbB1 = aB1;
    }

    // ---- main loop: both chunks per iteration, prefetched loads ----
    float4 cA0 = xpA[2 * lane], cA1 = xpA[2 * lane + 1];
    float4 cB0 = xpB[2 * lane], cB1 = xpB[2 * lane + 1];

    #pragma unroll 1
    for (int n = 0; n < ITERS; n++) {
        float4 nxA0, nxA1, nxB0, nxB1;
        if (n + 1 < ITERS) {
            nxA0 = xpA[(n + 1) * 64 + 2 * lane];
            nxA1 = xpA[(n + 1) * 64 + 2 * lane + 1];
            nxB0 = xpB[(n + 1) * 64 + 2 * lane];
            nxB1 = xpB[(n + 1) * 64 + 2 * lane + 1];
        }
        float xsA[8] = { cA0.x, cA0.y, cA0.z, cA0.w, cA1.x, cA1.y, cA1.z, cA1.w };
        float xsB[8] = { cB0.x, cB0.y, cB0.z, cB0.w, cB1.x, cB1.y, cB1.z, cB1.w };

        // lane-local contributions via Horner: w <- M w + v*x (both chunks)
        float wA0 = v0 * xsA[0], wA1 = v1 * xsA[0];
        float wB0 = v0 * xsB[0], wB1 = v1 * xsB[0];
        #pragma unroll
        for (int j = 1; j < 8; j++) {
            float tA0 = fmaf(nA1, wA0, wA1), tA1 = nA2 * wA0;
            float tB0 = fmaf(nA1, wB0, wB1), tB1 = nA2 * wB0;
            wA0 = fmaf(v0, xsA[j], tA0);  wA1 = fmaf(v1, xsA[j], tA1);
            wB0 = fmaf(v0, xsB[j], tB0);  wB1 = fmaf(v1, xsB[j], tB1);
        }
        // Kogge-Stone affine scans (levels in (c,d) form, row2 on the fly)
        #pragma unroll
        for (int l = 0; l < 5; l++) {
            int d = 1 << l;
            float t2 = nA2 * dL[l], t3 = fmaf(A1, dL[l], cL[l]);
            float uA0 = __shfl_up_sync(0xffffffffu, wA0, d);
            float uA1 = __shfl_up_sync(0xffffffffu, wA1, d);
            float uB0 = __shfl_up_sync(0xffffffffu, wB0, d);
            float uB1 = __shfl_up_sync(0xffffffffu, wB1, d);
            if (lane >= d) {
                wA0 = fmaf(cL[l], uA0, fmaf(dL[l], uA1, wA0));
                wA1 = fmaf(t2,    uA0, fmaf(t3,    uA1, wA1));
                wB0 = fmaf(cL[l], uB0, fmaf(dL[l], uB1, wB0));
                wB1 = fmaf(t2,    uB0, fmaf(t3,    uB1, wB1));
            }
        }
        float WA31_0 = __shfl_sync(0xffffffffu, wA0, 31);
        float WA31_1 = __shfl_sync(0xffffffffu, wA1, 31);
        float WB31_0 = __shfl_sync(0xffffffffu, wB0, 31);
        float WB31_1 = __shfl_sync(0xffffffffu, wB1, 31);
        float eA0 = __shfl_up_sync(0xffffffffu, wA0, 1);
        float eA1 = __shfl_up_sync(0xffffffffu, wA1, 1);
        float eB0 = __shfl_up_sync(0xffffffffu, wB0, 1);
        float eB1 = __shfl_up_sync(0xffffffffu, wB1, 1);
        if (lane == 0) { eA0 = eA1 = eB0 = eB1 = 0.f; }

        // states at the start of each lane's 8-sample block (Pl row2 on the fly)
        float Pt2 = nA2 * Pd, Pt3 = fmaf(A1, Pd, Pc);
        float sA1 = fmaf(Pc,  sbA0, fmaf(Pd,  sbA1, eA0));
        float sA2 = fmaf(Pt2, sbA0, fmaf(Pt3, sbA1, eA1));
        float sB1 = fmaf(Pc,  sbB0, fmaf(Pd,  sbB1, eB0));
        float sB2 = fmaf(Pt2, sbB0, fmaf(Pt3, sbB1, eB1));

        // DF2T replay (matches reference arithmetic), both chunks
        float ysA[8], ysB[8];
        #pragma unroll
        for (int j = 0; j < 8; j++) {
            float yA = fmaf(b0, xsA[j], sA1);
            float tA = fmaf(nA1, yA, fmaf(b1, xsA[j], sA2));
            sA2 = fmaf(nA2, yA, b2 * xsA[j]);
            sA1 = tA; ysA[j] = yA;
            float yB = fmaf(b0, xsB[j], sB1);
            float tB = fmaf(nA1, yB, fmaf(b1, xsB[j], sB2));
            sB2 = fmaf(nA2, yB, b2 * xsB[j]);
            sB1 = tB; ysB[j] = yB;
        }
        ypA[n * 64 + 2 * lane]     = make_float4(ysA[0], ysA[1], ysA[2], ysA[3]);
        ypA[n * 64 + 2 * lane + 1] = make_float4(ysA[4], ysA[5], ysA[6], ysA[7]);
        ypB[n * 64 + 2 * lane]     = make_float4(ysB[0], ysB[1], ysB[2], ysB[3]);
        ypB[n * 64 + 2 * lane + 1] = make_float4(ysB[4], ysB[5], ysB[6], ysB[7]);

        // carry: sb = M^256 sb + W31 (row2 of M^256 on the fly)
        float Mt2 = nA2 * Md, Mt3 = fmaf(A1, Md, Mc);
        float nA0s = fmaf(Mc,  sbA0, fmaf(Md,  sbA1, WA31_0));
        float nA1s = fmaf(Mt2, sbA0, fmaf(Mt3, sbA1, WA31_1));
        sbA0 = nA0s; sbA1 = nA1s;
        float nB0s = fmaf(Mc,  sbB0, fmaf(Md,  sbB1, WB31_0));
        float nB1s = fmaf(Mt2, sbB0, fmaf(Mt3, sbB1, WB31_1));
        sbB0 = nB0s; sbB1 = nB1s;

        cA0 = nxA0; cA1 = nxA1; cB0 = nxB0; cB1 = nxB1;
    }
}

extern "C" void kernel_launch(void* const* d_in, const int* in_sizes, int n_in,
                              void* d_out, int out_size) {
    const float* x  = (const float*)d_in[0];
    const float* fr = (const float*)d_in[1];
    const float* qr = (const float*)d_in[2];
    const float* gn = (const float*)d_in[3];
    float* y = (float*)d_out;

    int nc = in_sizes[0] / T_LEN;           // 32 channels
    if (nc > NC_MAX) nc = NC_MAX;
    if (nc < 1) nc = 1;

    int warps  = nc * (K_CHUNKS / 2);       // one warp per chunk pair
    int blocks = (warps + 3) / 4;           // 4 warps per 128-thread block
    peak_fused<<<blocks, 128>>>(x, y, fr, qr, gn, nc);
}

// round 12
// speedup vs baseline: 1.0863x; 1.0863x over previous
#include <cuda_runtime.h>
#include <math.h>

#define T_LEN    1048576
#define L_CHUNK  2048
#define K_CHUNKS (T_LEN / L_CHUNK)   // 512
#define SPI      256                 // samples per warp-iteration per chunk
#define ITERS    (L_CHUNK / SPI)     // 8
#define NC_MAX   32

// ILP=2 (two adjacent chunks per warp) + Horner lane contributions + compact
// (c,d) matrix powers + DEPTH-2 PREFETCH: loads for iteration n+2 are issued
// at the top of iteration n, giving 8 LDG.128 in flight per warp (~160
// lines/SM at 5 blocks) and two compute phases of scoreboard slack —
// depth-1 prefetch left every warp stalling on DRAM latency each iteration
// (R11: occupancy up, DRAM% flat at 62%). Full unroll makes the rotation
// pure register renaming.
__global__ __launch_bounds__(128, 5) void peak_fused(
    const float* __restrict__ x, float* __restrict__ y,
    const float* __restrict__ freq_raw, const float* __restrict__ Q_raw,
    const float* __restrict__ gain, int nc)
{
    int tid  = threadIdx.x;
    int lane = tid & 31;
    int gwid = blockIdx.x * 4 + (tid >> 5);          // warp id, 2 chunks each
    int ch = gwid / (K_CHUNKS / 2);
    int k0 = (gwid % (K_CHUNKS / 2)) * 2;            // first of the chunk pair
    if (ch >= nc) return;

    // ---- fp32 coefficient setup (per-warp, transient registers) ----
    const float SR = 44100.0f, MIN_F = 33.0f, MAX_F = 17500.0f, MIN_Q = 0.2f, MAX_Q = 20.0f;
    const float PI = 3.14159265358979323846f;
    float fr = freq_raw[0], qr = Q_raw[0], gn = gain[0];
    float freq = 1.0f / (1.0f + expf(-fr)) * (MAX_F - MIN_F) + MIN_F;
    float Q    = 1.0f / (1.0f + expf(-qr)) * (MAX_Q - MIN_Q) + MIN_Q;
    float w0c  = 2.0f * PI * freq / SR;
    float Ag   = powf(10.0f, gn * 0.025f);
    float alpha = sinf(w0c) / (2.0f * Q);
    float a0inv = 1.0f / (1.0f + alpha / Ag);
    float b0 = (1.0f + alpha * Ag) * a0inv;
    float b1 = (-2.0f * cosf(w0c)) * a0inv;
    float b2 = (1.0f - alpha * Ag) * a0inv;
    float A1 = b1;
    float A2 = (1.0f - alpha / Ag) * a0inv;
    float nA1 = -A1, nA2 = -A2;                       // M = [[-A1,1],[-A2,0]]
    float v0 = fmaf(nA1, b0, b1), v1 = fmaf(nA2, b0, b2);

    // p2[j] ~ M^(2^j) in (c,d) form, j = 0..8.
    float pc[9], pd[9];
    pc[0] = nA1; pd[0] = 1.0f;
    #pragma unroll
    for (int j = 1; j < 9; j++) {
        float c = pc[j-1], d = pd[j-1];
        pc[j] = fmaf(c, c, (nA2 * d) * d);
        pd[j] = d * fmaf(A1, d, 2.0f * c);
    }

    // scan levels l=0..4: (cL,dL) = M^(8*2^l) = p2[l+3]
    float cL[5], dL[5];
    #pragma unroll
    for (int l = 0; l < 5; l++) { cL[l] = pc[l+3]; dL[l] = pd[l+3]; }

    // Pl = M^(8*lane); Rl = M^(8*(31-lane)) (warmup only). Identity = (1,0).
    float Pc = 1.f, Pd = 0.f;
    #pragma unroll
    for (int l = 0; l < 5; l++) {
        if ((lane >> l) & 1) {
            float dd = Pd * pd[l+3];
            float c  = fmaf(Pc, pc[l+3], nA2 * dd);
            float d  = fmaf(Pc, pd[l+3], fmaf(Pd, pc[l+3], A1 * dd));
            Pc = c; Pd = d;
        }
    }
    float Rc = 1.f, Rd = 0.f;
    {
        int rl = 31 - lane;
        #pragma unroll
        for (int l = 0; l < 5; l++) {
            if ((rl >> l) & 1) {
                float dd = Rd * pd[l+3];
                float c  = fmaf(Rc, pc[l+3], nA2 * dd);
                float d  = fmaf(Rc, pd[l+3], fmaf(Rd, pc[l+3], A1 * dd));
                Rc = c; Rd = d;
            }
        }
    }
    float Mc = pc[8], Md = pd[8];                    // M^256 carry, (c,d) form

    size_t offA = (size_t)ch * T_LEN + (size_t)k0 * L_CHUNK;
    size_t offB = offA + L_CHUNK;
    const float4* xpA = (const float4*)(x + offA);
    const float4* xpB = (const float4*)(x + offB);
    float4*       ypA = (float4*)(y + offA);
    float4*       ypB = (float4*)(y + offB);

    // ---- warmups (both chunks, interleaved for MLP) ----
    float sbA0 = 0.f, sbA1 = 0.f, sbB0 = 0.f, sbB1 = 0.f;
    {
        float4 wa0, wa1, wb0, wb1;
        bool hasA = (k0 > 0);
        if (hasA) {
            const float4* wp = (const float4*)(x + offA - SPI);
            wa0 = wp[2 * lane]; wa1 = wp[2 * lane + 1];
        }
        {
            const float4* wp = (const float4*)(x + offB - SPI);
            wb0 = wp[2 * lane]; wb1 = wp[2 * lane + 1];
        }
        float wxA[8] = { wa0.x, wa0.y, wa0.z, wa0.w, wa1.x, wa1.y, wa1.z, wa1.w };
        float wxB[8] = { wb0.x, wb0.y, wb0.z, wb0.w, wb1.x, wb1.y, wb1.z, wb1.w };
        // Horner: h <- M h + v*x
        float hA0 = v0 * wxA[0], hA1 = v1 * wxA[0];
        float hB0 = v0 * wxB[0], hB1 = v1 * wxB[0];
        #pragma unroll
        for (int j = 1; j < 8; j++) {
            float tA0 = fmaf(nA1, hA0, hA1), tA1 = nA2 * hA0;
            float tB0 = fmaf(nA1, hB0, hB1), tB1 = nA2 * hB0;
            hA0 = fmaf(v0, wxA[j], tA0);  hA1 = fmaf(v1, wxA[j], tA1);
            hB0 = fmaf(v0, wxB[j], tB0);  hB1 = fmaf(v1, wxB[j], tB1);
        }
        // position weight: a = R * h, R row2 reconstructed from (Rc,Rd)
        float Rt2 = nA2 * Rd, Rt3 = fmaf(A1, Rd, Rc);
        float aA0 = fmaf(Rc, hA0, Rd * hA1);
        float aA1 = fmaf(Rt2, hA0, Rt3 * hA1);
        float aB0 = fmaf(Rc, hB0, Rd * hB1);
        float aB1 = fmaf(Rt2, hB0, Rt3 * hB1);
        if (!hasA) { aA0 = 0.f; aA1 = 0.f; }
        #pragma unroll
        for (int d = 16; d > 0; d >>= 1) {
            aA0 += __shfl_xor_sync(0xffffffffu, aA0, d);
            aA1 += __shfl_xor_sync(0xffffffffu, aA1, d);
            aB0 += __shfl_xor_sync(0xffffffffu, aB0, d);
            aB1 += __shfl_xor_sync(0xffffffffu, aB1, d);
        }
        if (hasA) { sbA0 = aA0; sbA1 = aA1; }
        sbB0 = aB0; sbB1 = aB1;
    }

    // ---- main loop: depth-2 prefetch double buffers, fully unrolled ----
    float4 bufA0[2], bufA1[2], bufB0[2], bufB1[2];
    bufA0[0] = xpA[2 * lane];      bufA1[0] = xpA[2 * lane + 1];
    bufB0[0] = xpB[2 * lane];      bufB1[0] = xpB[2 * lane + 1];
    bufA0[1] = xpA[64 + 2 * lane]; bufA1[1] = xpA[64 + 2 * lane + 1];
    bufB0[1] = xpB[64 + 2 * lane]; bufB1[1] = xpB[64 + 2 * lane + 1];

    #pragma unroll
    for (int n = 0; n < ITERS; n++) {
        const int b = n & 1;
        float4 cA0 = bufA0[b], cA1 = bufA1[b];
        float4 cB0 = bufB0[b], cB1 = bufB1[b];
        if (n + 2 < ITERS) {
            bufA0[b] = xpA[(n + 2) * 64 + 2 * lane];
            bufA1[b] = xpA[(n + 2) * 64 + 2 * lane + 1];
            bufB0[b] = xpB[(n + 2) * 64 + 2 * lane];
            bufB1[b] = xpB[(n + 2) * 64 + 2 * lane + 1];
        }
        float xsA[8] = { cA0.x, cA0.y, cA0.z, cA0.w, cA1.x, cA1.y, cA1.z, cA1.w };
        float xsB[8] = { cB0.x, cB0.y, cB0.z, cB0.w, cB1.x, cB1.y, cB1.z, cB1.w };

        // lane-local contributions via Horner: w <- M w + v*x (both chunks)
        float wA0 = v0 * xsA[0], wA1 = v1 * xsA[0];
        float wB0 = v0 * xsB[0], wB1 = v1 * xsB[0];
        #pragma unroll
        for (int j = 1; j < 8; j++) {
            float tA0 = fmaf(nA1, wA0, wA1), tA1 = nA2 * wA0;
            float tB0 = fmaf(nA1, wB0, wB1), tB1 = nA2 * wB0;
            wA0 = fmaf(v0, xsA[j], tA0);  wA1 = fmaf(v1, xsA[j], tA1);
            wB0 = fmaf(v0, xsB[j], tB0);  wB1 = fmaf(v1, xsB[j], tB1);
        }
        // Kogge-Stone affine scans (levels in (c,d) form, row2 on the fly)
        #pragma unroll
        for (int l = 0; l < 5; l++) {
            int d = 1 << l;
            float t2 = nA2 * dL[l], t3 = fmaf(A1, dL[l], cL[l]);
            float uA0 = __shfl_up_sync(0xffffffffu, wA0, d);
            float uA1 = __shfl_up_sync(0xffffffffu, wA1, d);
            float uB0 = __shfl_up_sync(0xffffffffu, wB0, d);
            float uB1 = __shfl_up_sync(0xffffffffu, wB1, d);
            if (lane >= d) {
                wA0 = fmaf(cL[l], uA0, fmaf(dL[l], uA1, wA0));
                wA1 = fmaf(t2,    uA0, fmaf(t3,    uA1, wA1));
                wB0 = fmaf(cL[l], uB0, fmaf(dL[l], uB1, wB0));
                wB1 = fmaf(t2,    uB0, fmaf(t3,    uB1, wB1));
            }
        }
        float WA31_0 = __shfl_sync(0xffffffffu, wA0, 31);
        float WA31_1 = __shfl_sync(0xffffffffu, wA1, 31);
        float WB31_0 = __shfl_sync(0xffffffffu, wB0, 31);
        float WB31_1 = __shfl_sync(0xffffffffu, wB1, 31);
        float eA0 = __shfl_up_sync(0xffffffffu, wA0, 1);
        float eA1 = __shfl_up_sync(0xffffffffu, wA1, 1);
        float eB0 = __shfl_up_sync(0xffffffffu, wB0, 1);
        float eB1 = __shfl_up_sync(0xffffffffu, wB1, 1);
        if (lane == 0) { eA0 = eA1 = eB0 = eB1 = 0.f; }

        // states at the start of each lane's 8-sample block (Pl row2 on the fly)
        float Pt2 = nA2 * Pd, Pt3 = fmaf(A1, Pd, Pc);
        float sA1 = fmaf(Pc,  sbA0, fmaf(Pd,  sbA1, eA0));
        float sA2 = fmaf(Pt2, sbA0, fmaf(Pt3, sbA1, eA1));
        float sB1 = fmaf(Pc,  sbB0, fmaf(Pd,  sbB1, eB0));
        float sB2 = fmaf(Pt2, sbB0, fmaf(Pt3, sbB1, eB1));

        // DF2T replay (matches reference arithmetic), both chunks
        float ysA[8], ysB[8];
        #pragma unroll
        for (int j = 0; j < 8; j++) {
            float yA = fmaf(b0, xsA[j], sA1);
            float tA = fmaf(nA1, yA, fmaf(b1, xsA[j], sA2));
            sA2 = fmaf(nA2, yA, b2 * xsA[j]);
            sA1 = tA; ysA[j] = yA;
            float yB = fmaf(b0, xsB[j], sB1);
            float tB = fmaf(nA1, yB, fmaf(b1, xsB[j], sB2));
            sB2 = fmaf(nA2, yB, b2 * xsB[j]);
            sB1 = tB; ysB[j] = yB;
        }
        ypA[n * 64 + 2 * lane]     = make_float4(ysA[0], ysA[1], ysA[2], ysA[3]);
        ypA[n * 64 + 2 * lane + 1] = make_float4(ysA[4], ysA[5], ysA[6], ysA[7]);
        ypB[n * 64 + 2 * lane]     = make_float4(ysB[0], ysB[1], ysB[2], ysB[3]);
        ypB[n * 64 + 2 * lane + 1] = make_float4(ysB[4], ysB[5], ysB[6], ysB[7]);

        // carry: sb = M^256 sb + W31 (row2 of M^256 on the fly)
        float Mt2 = nA2 * Md, Mt3 = fmaf(A1, Md, Mc);
        float nA0s = fmaf(Mc,  sbA0, fmaf(Md,  sbA1, WA31_0));
        float nA1s = fmaf(Mt2, sbA0, fmaf(Mt3, sbA1, WA31_1));
        sbA0 = nA0s; sbA1 = nA1s;
        float nB0s = fmaf(Mc,  sbB0, fmaf(Md,  sbB1, WB31_0));
        float nB1s = fmaf(Mt2, sbB0, fmaf(Mt3, sbB1, WB31_1));
        sbB0 = nB0s; sbB1 = nB1s;
    }
}

extern "C" void kernel_launch(void* const* d_in, const int* in_sizes, int n_in,
                              void* d_out, int out_size) {
    const float* x  = (const float*)d_in[0];
    const float* fr = (const float*)d_in[1];
    const float* qr = (const float*)d_in[2];
    const float* gn = (const float*)d_in[3];
    float* y = (float*)d_out;

    int nc = in_sizes[0] / T_LEN;           // 32 channels
    if (nc > NC_MAX) nc = NC_MAX;
    if (nc < 1) nc = 1;

    int warps  = nc * (K_CHUNKS / 2);       // one warp per chunk pair
    int blocks = (warps + 3) / 4;           // 4 warps per 128-thread block
    peak_fused<<<blocks, 128>>>(x, y, fr, qr, gn, nc);
}